// round 15
// baseline (speedup 1.0000x reference)
#include <cuda_runtime.h>

#define TPB  256
#define OPT  7     // outputs per thread: 293 blocks = single balanced wave @ 2 CTA/SM

typedef unsigned long long u64;

// ---- packed f32x2 helpers (sm_103a FFMA2 path, PTX-only) ----
__device__ __forceinline__ u64 pack2(float lo, float hi) {
    u64 r; asm("mov.b64 %0, {%1, %2};" : "=l"(r) : "f"(lo), "f"(hi)); return r;
}
__device__ __forceinline__ void unpack2(u64 v, float& lo, float& hi) {
    asm("mov.b64 {%0, %1}, %2;" : "=f"(lo), "=f"(hi) : "l"(v));
}
__device__ __forceinline__ u64 fma2(u64 a, u64 b, u64 c) {
    u64 d; asm("fma.rn.f32x2 %0, %1, %2, %3;" : "=l"(d) : "l"(a), "l"(b), "l"(c)); return d;
}

// GMP DPD, real-part output (harness drops imag):
//   Re(y[n]) = sum_{d=0..3} ( a[n-d]*wr_d(n) - b[n-d]*wi_d(n) )
//   w_d(n)   = c(1,d) + sum_{off=-2..2} P_{d,off}(s[n-d+off]),  s = |x|^2
//   P(s)     = s*(c2 + s*(c4 + s*c6))     (Horner; no r4/r6 register arrays)
// x zero-padded outside [0,N) (matches reference delay/lag/lead concats).
//
// Coefficient column order (reference basis):
//   [0:16)  main : order {1,3,5,7} x delay {0..3}
//   [16:40) lag  : order {3,5,7} x lag  {1,2} x delay {0..3}
//   [40:64) lead : order {3,5,7} x lead {1,2} x delay {0..3}
// (c2,c4,c6) triples per (d, off):
//   off= 0: ( 4+d,  8+d, 12+d)   off=-1: (16+d, 24+d, 32+d)
//   off=-2: (20+d, 28+d, 36+d)   off=+1: (40+d, 48+d, 56+d)
//   off=+2: (44+d, 52+d, 60+d)
__global__ __launch_bounds__(TPB, 2)   // 2 CTAs/SM (<=128 regs), NOT 4: avoid spills
void dpd_kernel(const float* __restrict__ xr, const float* __restrict__ xi,
                const float* __restrict__ cr, const float* __restrict__ ci,
                float* __restrict__ out, int n)
{
    __shared__ u64 scp[64];                        // packed (cr, ci)
    int tid = threadIdx.x;
    if (tid < 64) scp[tid] = pack2(__ldg(cr + tid), __ldg(ci + tid));
    __syncthreads();

    int base = (blockIdx.x * TPB + tid) * OPT;     // outputs [base, base+OPT)
    if (base >= n) return;

    // Halo: global positions base-5 .. base+OPT+1 -> local t in [0, OPT+6].
    u64 r2p[OPT + 7];                              // (s, s) packed, s = |x|^2
    u64 abp[OPT + 5];                              // (a, -b); t in [2, OPT+4] used
    int m0 = base - 5;
    bool interior = (m0 >= 0) && (base + OPT + 2 <= n);
#pragma unroll
    for (int t = 0; t < OPT + 7; t++) {
        float a, b;
        if (interior) {
            a = __ldg(xr + m0 + t);
            b = __ldg(xi + m0 + t);
        } else {
            int m = m0 + t;
            bool ok = (m >= 0) && (m < n);
            a = ok ? __ldg(xr + m) : 0.0f;
            b = ok ? __ldg(xi + m) : 0.0f;
        }
        float s = fmaf(a, a, b * b);
        r2p[t] = pack2(s, s);
        if (t >= 2 && t <= OPT + 4) abp[t] = pack2(a, -b);
    }

    u64 yp[OPT];                                   // packed (a*wr | -b*wi) accum
    u64 z = pack2(0.0f, 0.0f);
#pragma unroll
    for (int q = 0; q < OPT; q++) yp[q] = z;

    // d-outer: each packed coeff loaded once (uniform LDS -> broadcast),
    // amortized over OPT=7 outputs.
#pragma unroll
    for (int d = 0; d < 4; d++) {
        u64 wp[OPT];
        u64 c0 = scp[d];                           // order-1 main term
#pragma unroll
        for (int q = 0; q < OPT; q++) wp[q] = c0;

        // Horner triple for (d, OFF): wp += s*(c2 + s*(c4 + s*c6))
#define HACC(C2, C4, C6, OFF) {                                                    \
        u64 c6v = scp[(C6)], c4v = scp[(C4)], c2v = scp[(C2)];                      \
        _Pragma("unroll")                                                           \
        for (int q = 0; q < OPT; q++) {                                             \
            u64 s = r2p[q - d + 5 + (OFF)];                                         \
            u64 p = fma2(s, c6v, c4v);                                              \
            p     = fma2(s, p,   c2v);                                              \
            wp[q] = fma2(s, p, wp[q]);                                              \
        } }

        HACC( 4 + d,  8 + d, 12 + d,  0)           // main
        HACC(16 + d, 24 + d, 32 + d, -1)           // lag 1
        HACC(20 + d, 28 + d, 36 + d, -2)           // lag 2
        HACC(40 + d, 48 + d, 56 + d,  1)           // lead 1
        HACC(44 + d, 52 + d, 60 + d,  2)           // lead 2
#undef HACC

        // yp += (a, -b) * (wr, wi)   [lanes: a*wr | -b*wi]
#pragma unroll
        for (int q = 0; q < OPT; q++)
            yp[q] = fma2(abp[q - d + 5], wp[q], yp[q]);
    }

    // Horizontal add per output: Re(y) = a*wr_sum + (-b)*wi_sum.
#pragma unroll
    for (int q = 0; q < OPT; q++) {
        int g = base + q;
        if (g < n) {
            float lo, hi;
            unpack2(yp[q], lo, hi);
            out[g] = lo + hi;
        }
    }
}

extern "C" void kernel_launch(void* const* d_in, const int* in_sizes, int n_in,
                              void* d_out, int out_size)
{
    // Confirmed layout: d_in = {x_real[N], x_imag[N], coeffs_real[64],
    // coeffs_imag[64]}, all float32; out = float32[N] (real part only).
    const float* xr = (const float*)d_in[0];
    const float* xi = (const float*)d_in[1];
    const float* cr = (const float*)d_in[2];
    const float* ci = (const float*)d_in[3];

    int n = in_sizes[0];
    if (n > out_size) n = out_size;                // never write past d_out

    int threads = (n + OPT - 1) / OPT;
    int blocks  = (threads + TPB - 1) / TPB;       // 293 @ N=524288: one wave
    dpd_kernel<<<blocks, TPB>>>(xr, xi, cr, ci, (float*)d_out, n);
}

// round 16
// speedup vs baseline: 1.7797x; 1.7797x over previous
#include <cuda_runtime.h>

#define TPB  128
#define OPT  4                   // outputs per thread (strided by TPB)
#define CPS  7                   // CTAs/SM: 1024 blocks <= 148*7 -> single wave
#define SH   (TPB * OPT + 7)     // staged positions: [blk0-5, blk0+TPB*OPT+2)

typedef unsigned long long u64;

// ---- packed f32x2 helpers (sm_103a FFMA2 path, PTX-only) ----
__device__ __forceinline__ u64 pack2(float lo, float hi) {
    u64 r; asm("mov.b64 %0, {%1, %2};" : "=l"(r) : "f"(lo), "f"(hi)); return r;
}
__device__ __forceinline__ void unpack2(u64 v, float& lo, float& hi) {
    asm("mov.b64 {%0, %1}, %2;" : "=f"(lo), "=f"(hi) : "l"(v));
}
__device__ __forceinline__ u64 fma2(u64 a, u64 b, u64 c) {
    u64 d; asm("fma.rn.f32x2 %0, %1, %2, %3;" : "=l"(d) : "l"(a), "l"(b), "l"(c)); return d;
}

// GMP DPD, real-part output (harness drops imag):
//   Re(y[n]) = sum_{d=0..3} ( a[n-d]*wr_d(n) - b[n-d]*wi_d(n) )
//   w_d(n)   = c(1,d) + sum_{off=-2..2} P_{d,off}(s[n-d+off]),  s = |x|^2
//   P(s)     = s*(c2 + s*(c4 + s*c6))          (Horner in s)
// x zero-padded outside [0,N) (matches reference delay/lag/lead concats);
// padding is applied once in the staging phase, so the compute loop is
// guard-free.
//
// Shared staging: s_sm[i] = (s,s) packed, ab_sm[i] = (a,-b) packed for block
// positions [blk0-5, blk0+TPB*OPT+2). Threads own STRIDED outputs
// g = blk0 + tid + q*TPB  ->  all smem reads are lane-consecutive u64
// (conflict-free) and all LDG/STG are fully coalesced. Registers stay ~60
// (no private halo arrays) -> 7 CTAs/SM, 28 warps/SM for latency hiding.
//
// Coefficient column order (reference basis):
//   [0:16)  main : order {1,3,5,7} x delay {0..3}
//   [16:40) lag  : order {3,5,7} x lag  {1,2} x delay {0..3}
//   [40:64) lead : order {3,5,7} x lead {1,2} x delay {0..3}
// (c2,c4,c6) triples per (d, off):
//   off= 0: ( 4+d,  8+d, 12+d)   off=-1: (16+d, 24+d, 32+d)
//   off=-2: (20+d, 28+d, 36+d)   off=+1: (40+d, 48+d, 56+d)
//   off=+2: (44+d, 52+d, 60+d)
__global__ __launch_bounds__(TPB, CPS)
void dpd_kernel(const float* __restrict__ xr, const float* __restrict__ xi,
                const float* __restrict__ cr, const float* __restrict__ ci,
                float* __restrict__ out, int n)
{
    __shared__ u64 s_sm[SH];      // (s, s) duplicated
    __shared__ u64 ab_sm[SH];     // (a, -b)
    __shared__ u64 scp[64];       // packed (cr, ci)

    int tid  = threadIdx.x;
    int blk0 = blockIdx.x * (TPB * OPT);
    int lo   = blk0 - 5;

    if (tid < 64) scp[tid] = pack2(__ldg(cr + tid), __ldg(ci + tid));

    // Stage: coalesced loads, zero-pad OOB, precompute packed pairs.
#pragma unroll
    for (int k = 0; k < (SH + TPB - 1) / TPB; k++) {
        int i = tid + k * TPB;
        if (i < SH) {
            int m = lo + i;
            bool ok = (m >= 0) && (m < n);
            float a = ok ? __ldg(xr + m) : 0.0f;
            float b = ok ? __ldg(xi + m) : 0.0f;
            float s = fmaf(a, a, b * b);
            s_sm[i]  = pack2(s, s);
            ab_sm[i] = pack2(a, -b);
        }
    }
    __syncthreads();

    // Thread outputs: g(q) = blk0 + tid + q*TPB; local center = tid + q*TPB + 5.
    u64 yp[OPT];
    u64 z = pack2(0.0f, 0.0f);
#pragma unroll
    for (int q = 0; q < OPT; q++) yp[q] = z;

    int sb = tid + 5;             // local index of position g(q=0)

#pragma unroll
    for (int d = 0; d < 4; d++) {
        u64 wp[OPT];
        u64 c0 = scp[d];          // order-1 main term
#pragma unroll
        for (int q = 0; q < OPT; q++) wp[q] = c0;

        // Horner triple for (d, OFF): wp += s*(c2 + s*(c4 + s*c6))
        // s comes straight from smem (conflict-free LDS.64), used once.
#define HACC(C2, C4, C6, OFF) {                                                    \
        u64 c6v = scp[(C6)], c4v = scp[(C4)], c2v = scp[(C2)];                      \
        _Pragma("unroll")                                                           \
        for (int q = 0; q < OPT; q++) {                                             \
            u64 s = s_sm[sb + q * TPB - d + (OFF)];                                 \
            u64 p = fma2(s, c6v, c4v);                                              \
            p     = fma2(s, p,   c2v);                                              \
            wp[q] = fma2(s, p, wp[q]);                                              \
        } }

        HACC( 4 + d,  8 + d, 12 + d,  0)          // main
        HACC(16 + d, 24 + d, 32 + d, -1)          // lag 1
        HACC(20 + d, 28 + d, 36 + d, -2)          // lag 2
        HACC(40 + d, 48 + d, 56 + d,  1)          // lead 1
        HACC(44 + d, 52 + d, 60 + d,  2)          // lead 2
#undef HACC

        // yp += (a, -b) * (wr, wi)   [lanes: a*wr | -b*wi]
#pragma unroll
        for (int q = 0; q < OPT; q++) {
            u64 ab = ab_sm[sb + q * TPB - d];
            yp[q] = fma2(ab, wp[q], yp[q]);
        }
    }

    // Horizontal add per output: Re(y) = a*wr_sum + (-b)*wi_sum.
#pragma unroll
    for (int q = 0; q < OPT; q++) {
        int g = blk0 + tid + q * TPB;             // coalesced store
        if (g < n) {
            float lov, hiv;
            unpack2(yp[q], lov, hiv);
            out[g] = lov + hiv;
        }
    }
}

extern "C" void kernel_launch(void* const* d_in, const int* in_sizes, int n_in,
                              void* d_out, int out_size)
{
    // Confirmed layout: d_in = {x_real[N], x_imag[N], coeffs_real[64],
    // coeffs_imag[64]}, all float32; out = float32[N] (real part only).
    const float* xr = (const float*)d_in[0];
    const float* xi = (const float*)d_in[1];
    const float* cr = (const float*)d_in[2];
    const float* ci = (const float*)d_in[3];

    int n = in_sizes[0];
    if (n > out_size) n = out_size;               // never write past d_out

    int per_blk = TPB * OPT;
    int blocks  = (n + per_blk - 1) / per_blk;    // 1024 @ N=524288: one wave
    dpd_kernel<<<blocks, TPB>>>(xr, xi, cr, ci, (float*)d_out, n);
}

// round 17
// speedup vs baseline: 2.5590x; 1.4379x over previous
#include <cuda_runtime.h>

#define TPB  128
#define OPT  5     // outputs per thread; 820 blocks vs 888 resident -> ~1 wave
#define CPS  6     // 6 CTAs/SM = 24 warps/SM; reg cap 85 (est. need ~80)

typedef unsigned long long u64;

// ---- packed f32x2 helpers (sm_103a FFMA2 path, PTX-only) ----
__device__ __forceinline__ u64 pack2(float lo, float hi) {
    u64 r; asm("mov.b64 %0, {%1, %2};" : "=l"(r) : "f"(lo), "f"(hi)); return r;
}
__device__ __forceinline__ void unpack2(u64 v, float& lo, float& hi) {
    asm("mov.b64 {%0, %1}, %2;" : "=f"(lo), "=f"(hi) : "l"(v));
}
__device__ __forceinline__ u64 fma2(u64 a, u64 b, u64 c) {
    u64 d; asm("fma.rn.f32x2 %0, %1, %2, %3;" : "=l"(d) : "l"(a), "l"(b), "l"(c)); return d;
}

// GMP DPD, real-part output (harness drops imag):
//   Re(y[n]) = sum_{d=0..3} ( a[n-d]*wr_d(n) - b[n-d]*wi_d(n) )
//   w_d(n)   = c(1,d) + sum_{off=-2..2} P_{d,off}(s[n-d+off]),  s = |x|^2
//   P(s)     = s*(c2 + s*(c4 + s*c6))      (Horner; no r4/r6 arrays)
// x zero-padded outside [0,N) (matches reference delay/lag/lead concats).
//
// Design rationale (R14-R16 evidence): operands MUST live in registers
// (every smem-operand / spilled variant regressed 1.7x), so the only lever
// left is resident warps. OPT=5 Horner fits ~80 regs -> 6 CTAs/SM via
// __launch_bounds__(128,6) = 24 warps/SM at private-register operands.
//
// Coefficient column order (reference basis):
//   [0:16)  main : order {1,3,5,7} x delay {0..3}
//   [16:40) lag  : order {3,5,7} x lag  {1,2} x delay {0..3}
//   [40:64) lead : order {3,5,7} x lead {1,2} x delay {0..3}
// (c2,c4,c6) triples per (d, off):
//   off= 0: ( 4+d,  8+d, 12+d)   off=-1: (16+d, 24+d, 32+d)
//   off=-2: (20+d, 28+d, 36+d)   off=+1: (40+d, 48+d, 56+d)
//   off=+2: (44+d, 52+d, 60+d)
__global__ __launch_bounds__(TPB, CPS)
void dpd_kernel(const float* __restrict__ xr, const float* __restrict__ xi,
                const float* __restrict__ cr, const float* __restrict__ ci,
                float* __restrict__ out, int n)
{
    __shared__ u64 scp[64];                        // packed (cr, ci)
    int tid = threadIdx.x;
    if (tid < 64) scp[tid] = pack2(__ldg(cr + tid), __ldg(ci + tid));
    __syncthreads();

    int base = (blockIdx.x * TPB + tid) * OPT;     // outputs [base, base+OPT)
    if (base >= n) return;

    // Halo: global positions base-5 .. base+OPT+1 -> local t in [0, OPT+6].
    u64 r2p[OPT + 7];                              // (s, s) packed, s = |x|^2
    u64 abp[OPT + 5];                              // (a, -b); t in [2, OPT+4] used
    int m0 = base - 5;
    bool interior = (m0 >= 0) && (base + OPT + 2 <= n);
#pragma unroll
    for (int t = 0; t < OPT + 7; t++) {
        float a, b;
        if (interior) {
            a = __ldg(xr + m0 + t);
            b = __ldg(xi + m0 + t);
        } else {
            int m = m0 + t;
            bool ok = (m >= 0) && (m < n);
            a = ok ? __ldg(xr + m) : 0.0f;
            b = ok ? __ldg(xi + m) : 0.0f;
        }
        float s = fmaf(a, a, b * b);
        r2p[t] = pack2(s, s);
        if (t >= 2 && t <= OPT + 4) abp[t] = pack2(a, -b);
    }

    u64 yp[OPT];                                   // packed (a*wr | -b*wi) accum
    u64 z = pack2(0.0f, 0.0f);
#pragma unroll
    for (int q = 0; q < OPT; q++) yp[q] = z;

    // d-outer: each packed coeff loaded once (uniform LDS -> broadcast).
#pragma unroll
    for (int d = 0; d < 4; d++) {
        u64 wp[OPT];
        u64 c0 = scp[d];                           // order-1 main term
#pragma unroll
        for (int q = 0; q < OPT; q++) wp[q] = c0;

        // Horner triple for (d, OFF): wp += s*(c2 + s*(c4 + s*c6))
#define HACC(C2, C4, C6, OFF) {                                                    \
        u64 c6v = scp[(C6)], c4v = scp[(C4)], c2v = scp[(C2)];                      \
        _Pragma("unroll")                                                           \
        for (int q = 0; q < OPT; q++) {                                             \
            u64 s = r2p[q - d + 5 + (OFF)];                                         \
            u64 p = fma2(s, c6v, c4v);                                              \
            p     = fma2(s, p,   c2v);                                              \
            wp[q] = fma2(s, p, wp[q]);                                              \
        } }

        HACC( 4 + d,  8 + d, 12 + d,  0)           // main
        HACC(16 + d, 24 + d, 32 + d, -1)           // lag 1
        HACC(20 + d, 28 + d, 36 + d, -2)           // lag 2
        HACC(40 + d, 48 + d, 56 + d,  1)           // lead 1
        HACC(44 + d, 52 + d, 60 + d,  2)           // lead 2
#undef HACC

        // yp += (a, -b) * (wr, wi)   [lanes: a*wr | -b*wi]
#pragma unroll
        for (int q = 0; q < OPT; q++)
            yp[q] = fma2(abp[q - d + 5], wp[q], yp[q]);
    }

    // Horizontal add per output: Re(y) = a*wr_sum + (-b)*wi_sum.
#pragma unroll
    for (int q = 0; q < OPT; q++) {
        int g = base + q;
        if (g < n) {
            float lo, hi;
            unpack2(yp[q], lo, hi);
            out[g] = lo + hi;
        }
    }
}

extern "C" void kernel_launch(void* const* d_in, const int* in_sizes, int n_in,
                              void* d_out, int out_size)
{
    // Confirmed layout: d_in = {x_real[N], x_imag[N], coeffs_real[64],
    // coeffs_imag[64]}, all float32; out = float32[N] (real part only).
    const float* xr = (const float*)d_in[0];
    const float* xi = (const float*)d_in[1];
    const float* cr = (const float*)d_in[2];
    const float* ci = (const float*)d_in[3];

    int n = in_sizes[0];
    if (n > out_size) n = out_size;                // never write past d_out

    int threads = (n + OPT - 1) / OPT;
    int blocks  = (threads + TPB - 1) / TPB;       // 820 @ N=524288
    dpd_kernel<<<blocks, TPB>>>(xr, xi, cr, ci, (float*)d_out, n);
}